// round 1
// baseline (speedup 1.0000x reference)
#include <cuda_runtime.h>
#include <math.h>

#define BB 32
#define NN 3136
#define DD 384
#define HH 8
#define CC 48
#define BH 256          // BB*HH
#define ROWS 100352     // BB*NN
#define E3 1152         // 3*DD
#define NSPLIT 7
#define NCHUNK 448      // NN / NSPLIT

// Scratch (sanctioned __device__ globals; no allocations anywhere)
__device__ float g_qkv[(size_t)3 * BH * CC * NN];   // [3][bh][c][n]
__device__ float g_invn[2 * BH * CC];               // inv norms: q rows then k rows
__device__ float g_spart[(size_t)NSPLIT * BH * CC * CC];
__device__ float g_p[(size_t)BH * CC * CC];         // softmaxed attn
__device__ float g_o[(size_t)BH * CC * NN];         // attn @ v, [bh][c][n]

// ---------------------------------------------------------------------------
// K1: qkv = x @ qkv_w^T, scattered into [3][bh][c][n]
// 128x128 tile, BK=16, 256 threads, 8x8 per thread
// ---------------------------------------------------------------------------
__global__ __launch_bounds__(256) void k_qkv(const float* __restrict__ x,
                                             const float* __restrict__ w) {
    __shared__ float Xs[16][132];
    __shared__ float Ws[16][132];
    const int m0 = blockIdx.y * 128;
    const int e0 = blockIdx.x * 128;
    const int t  = threadIdx.x;
    const int tx = t & 15, ty = t >> 4;
    const int lk = (t & 3) * 4;   // k offset within tile for loads
    const int lr = t >> 2;        // row offset 0..63

    float acc[8][8];
#pragma unroll
    for (int i = 0; i < 8; i++)
#pragma unroll
        for (int j = 0; j < 8; j++) acc[i][j] = 0.f;

    for (int k0 = 0; k0 < DD; k0 += 16) {
#pragma unroll
        for (int p = 0; p < 2; p++) {
            int r = lr + 64 * p;
            float4 v = *(const float4*)(x + (size_t)(m0 + r) * DD + k0 + lk);
            Xs[lk + 0][r] = v.x; Xs[lk + 1][r] = v.y;
            Xs[lk + 2][r] = v.z; Xs[lk + 3][r] = v.w;
        }
#pragma unroll
        for (int p = 0; p < 2; p++) {
            int r = lr + 64 * p;
            float4 v = *(const float4*)(w + (size_t)(e0 + r) * DD + k0 + lk);
            Ws[lk + 0][r] = v.x; Ws[lk + 1][r] = v.y;
            Ws[lk + 2][r] = v.z; Ws[lk + 3][r] = v.w;
        }
        __syncthreads();
#pragma unroll
        for (int kk = 0; kk < 16; kk++) {
            float a[8], b[8];
#pragma unroll
            for (int mi = 0; mi < 2; mi++) {
                float4 v = *(const float4*)&Xs[kk][4 * tx + 64 * mi];
                a[4 * mi + 0] = v.x; a[4 * mi + 1] = v.y;
                a[4 * mi + 2] = v.z; a[4 * mi + 3] = v.w;
            }
#pragma unroll
            for (int ei = 0; ei < 2; ei++) {
                float4 v = *(const float4*)&Ws[kk][4 * ty + 64 * ei];
                b[4 * ei + 0] = v.x; b[4 * ei + 1] = v.y;
                b[4 * ei + 2] = v.z; b[4 * ei + 3] = v.w;
            }
#pragma unroll
            for (int i = 0; i < 8; i++)
#pragma unroll
                for (int j = 0; j < 8; j++) acc[i][j] += a[i] * b[j];
        }
        __syncthreads();
    }

    // scatter store: n-contiguous float4 per (e, mi)
#pragma unroll
    for (int ei = 0; ei < 2; ei++)
#pragma unroll
        for (int j = 0; j < 4; j++) {
            int e   = e0 + 4 * ty + j + 64 * ei;
            int s   = e / DD;
            int rem = e - s * DD;
            int h   = rem / CC;
            int c   = rem - h * CC;
#pragma unroll
            for (int mi = 0; mi < 2; mi++) {
                int m = m0 + 4 * tx + 64 * mi;
                int b_ = m / NN;
                int n  = m - b_ * NN;
                float* dst = g_qkv +
                    ((size_t)((s * BB + b_) * HH + h) * CC + c) * NN + n;
                *(float4*)dst = make_float4(acc[4 * mi + 0][4 * ei + j],
                                            acc[4 * mi + 1][4 * ei + j],
                                            acc[4 * mi + 2][4 * ei + j],
                                            acc[4 * mi + 3][4 * ei + j]);
            }
        }
}

// ---------------------------------------------------------------------------
// K2: inverse L2 norms of q and k rows (over n). One warp per row.
// ---------------------------------------------------------------------------
__global__ __launch_bounds__(256) void k_norm() {
    int row  = blockIdx.x * 8 + (threadIdx.x >> 5);   // 0..24575
    int lane = threadIdx.x & 31;
    const float4* p = (const float4*)(g_qkv + (size_t)row * NN);
    float s = 0.f;
    for (int i = lane; i < NN / 4; i += 32) {
        float4 v = p[i];
        s += v.x * v.x + v.y * v.y + v.z * v.z + v.w * v.w;
    }
#pragma unroll
    for (int o = 16; o; o >>= 1) s += __shfl_xor_sync(0xffffffffu, s, o);
    if (lane == 0) g_invn[row] = 1.f / fmaxf(sqrtf(s), 1e-12f);
}

// ---------------------------------------------------------------------------
// K3a: partial S[c][d] = sum_n q[c][n] k[d][n] over an n-chunk (deterministic)
// grid (BH, NSPLIT), 256 threads, 3x3 outputs per thread
// ---------------------------------------------------------------------------
__global__ __launch_bounds__(256) void k_qk() {
    __shared__ float qs[48][68];
    __shared__ float ks[48][68];
    const int bh = blockIdx.x;
    const int n0 = blockIdx.y * NCHUNK;
    const int t  = threadIdx.x;
    const int ci = t >> 4, dj = t & 15;

    const float* qb = g_qkv + (size_t)bh * CC * NN;
    const float* kb = g_qkv + (size_t)(BH + bh) * CC * NN;

    float acc[3][3] = {};
    for (int cc = 0; cc < NCHUNK; cc += 64) {
        int nb = n0 + cc;
#pragma unroll
        for (int jj = 0; jj < 3; jj++) {
            int idx = t + 256 * jj;
            int c = idx >> 4, f = idx & 15;
            *(float4*)&qs[c][4 * f] = *(const float4*)(qb + (size_t)c * NN + nb + 4 * f);
            *(float4*)&ks[c][4 * f] = *(const float4*)(kb + (size_t)c * NN + nb + 4 * f);
        }
        __syncthreads();
#pragma unroll 8
        for (int nn = 0; nn < 64; nn++) {
            float a0 = qs[3 * ci + 0][nn];
            float a1 = qs[3 * ci + 1][nn];
            float a2 = qs[3 * ci + 2][nn];
            float b0 = ks[3 * dj + 0][nn];
            float b1 = ks[3 * dj + 1][nn];
            float b2 = ks[3 * dj + 2][nn];
            acc[0][0] += a0 * b0; acc[0][1] += a0 * b1; acc[0][2] += a0 * b2;
            acc[1][0] += a1 * b0; acc[1][1] += a1 * b1; acc[1][2] += a1 * b2;
            acc[2][0] += a2 * b0; acc[2][1] += a2 * b1; acc[2][2] += a2 * b2;
        }
        __syncthreads();
    }
    float* out = g_spart + ((size_t)blockIdx.y * BH + bh) * (CC * CC);
#pragma unroll
    for (int i = 0; i < 3; i++)
#pragma unroll
        for (int j = 0; j < 3; j++)
            out[(3 * ci + i) * CC + (3 * dj + j)] = acc[i][j];
}

// ---------------------------------------------------------------------------
// K3b: reduce partials, apply inv-norms + temperature, row softmax -> g_p
// grid BH, 64 threads
// ---------------------------------------------------------------------------
__global__ __launch_bounds__(64) void k_softmax(const float* __restrict__ temp) {
    __shared__ float S[48][48];
    const int bh = blockIdx.x;
    const int t  = threadIdx.x;
    const float tp = temp[bh % HH];
    for (int idx = t; idx < CC * CC; idx += 64) {
        float s = 0.f;
#pragma unroll
        for (int p = 0; p < NSPLIT; p++)
            s += g_spart[((size_t)p * BH + bh) * (CC * CC) + idx];
        int c = idx / CC, d = idx - c * CC;
        s *= g_invn[bh * CC + c] * g_invn[BH * CC + bh * CC + d] * tp;
        S[c][d] = s;
    }
    __syncthreads();
    if (t < 48) {
        float mx = -1e30f;
#pragma unroll
        for (int d = 0; d < 48; d++) mx = fmaxf(mx, S[t][d]);
        float sum = 0.f;
#pragma unroll
        for (int d = 0; d < 48; d++) {
            float e = __expf(S[t][d] - mx);
            S[t][d] = e;
            sum += e;
        }
        float inv = 1.f / sum;
#pragma unroll
        for (int d = 0; d < 48; d++)
            g_p[(size_t)bh * (CC * CC) + t * CC + d] = S[t][d] * inv;
    }
}

// ---------------------------------------------------------------------------
// K4: out[c][n] = sum_d P[c][d] * v[d][n]   (per bh, 128-n tiles)
// grid (BH, 25), 256 threads: 8 c-groups x 32 n-float4s, 6 c x 4 n per thread
// ---------------------------------------------------------------------------
__global__ __launch_bounds__(256) void k_av() {
    __shared__ float P[48][49];
    __shared__ float Vs[48][132];
    const int bh = blockIdx.x;
    const int n0 = blockIdx.y * 128;
    const int t  = threadIdx.x;
    const int nrem = NN - n0;   // 128 except last tile (64)

    for (int idx = t; idx < CC * CC; idx += 256) {
        int c = idx / CC;
        P[c][idx - c * CC] = g_p[(size_t)bh * (CC * CC) + idx];
    }
    const float* vb = g_qkv + (size_t)(2 * BH + bh) * CC * NN;
#pragma unroll
    for (int jj = 0; jj < 6; jj++) {
        int idx = t + 256 * jj;
        int d = idx >> 5, f = idx & 31;
        if (4 * f < nrem)
            *(float4*)&Vs[d][4 * f] = *(const float4*)(vb + (size_t)d * NN + n0 + 4 * f);
    }
    __syncthreads();

    const int fi = t & 31;
    const int cg = t >> 5;
    if (4 * fi < nrem) {
        float acc[6][4] = {};
#pragma unroll
        for (int d = 0; d < 48; d++) {
            float4 v = *(const float4*)&Vs[d][4 * fi];
#pragma unroll
            for (int i = 0; i < 6; i++) {
                float p = P[6 * cg + i][d];
                acc[i][0] += p * v.x; acc[i][1] += p * v.y;
                acc[i][2] += p * v.z; acc[i][3] += p * v.w;
            }
        }
        float* ob = g_o + (size_t)bh * CC * NN;
#pragma unroll
        for (int i = 0; i < 6; i++)
            *(float4*)(ob + (size_t)(6 * cg + i) * NN + n0 + 4 * fi) =
                make_float4(acc[i][0], acc[i][1], acc[i][2], acc[i][3]);
    }
}

// ---------------------------------------------------------------------------
// K5: final = out_bnd @ proj_w^T + proj_b   (A gathered from [bh][c][n])
// 128x128 tile, BK=16, 256 threads, 8x8 per thread; stores e-contiguous
// ---------------------------------------------------------------------------
__global__ __launch_bounds__(256) void k_proj(const float* __restrict__ w,
                                              const float* __restrict__ bias,
                                              float* __restrict__ out) {
    __shared__ float As[16][132];
    __shared__ float Ws[16][132];
    const int m0 = blockIdx.y * 128;
    const int e0 = blockIdx.x * 128;
    const int t  = threadIdx.x;
    const int tx = t & 15, ty = t >> 4;
    const int lm  = (t & 31) * 4;   // m offset for A loads (float4)
    const int lk8 = t >> 5;         // k offset 0..7 (+8 second pass)
    const int lwk = (t & 3) * 4;    // W load k offset
    const int lwr = t >> 2;         // W load row offset

    // b, n for this thread's A-load column (m fixed across k-loop)
    const int am = m0 + lm;
    const int ab = am / NN;
    const int an = am - ab * NN;

    float acc[8][8];
#pragma unroll
    for (int i = 0; i < 8; i++)
#pragma unroll
        for (int j = 0; j < 8; j++) acc[i][j] = 0.f;

    for (int k0 = 0; k0 < DD; k0 += 16) {
#pragma unroll
        for (int p = 0; p < 2; p++) {
            int k = k0 + lk8 + 8 * p;
            int h = k / CC;
            int c = k - h * CC;
            const float* src = g_o + ((size_t)(ab * HH + h) * CC + c) * NN + an;
            *(float4*)&As[lk8 + 8 * p][lm] = *(const float4*)src;
        }
#pragma unroll
        for (int p = 0; p < 2; p++) {
            int r = lwr + 64 * p;
            float4 v = *(const float4*)(w + (size_t)(e0 + r) * DD + k0 + lwk);
            Ws[lwk + 0][r] = v.x; Ws[lwk + 1][r] = v.y;
            Ws[lwk + 2][r] = v.z; Ws[lwk + 3][r] = v.w;
        }
        __syncthreads();
#pragma unroll
        for (int kk = 0; kk < 16; kk++) {
            float a[8], b[8];
#pragma unroll
            for (int mi = 0; mi < 2; mi++) {
                float4 v = *(const float4*)&As[kk][4 * ty + 64 * mi];
                a[4 * mi + 0] = v.x; a[4 * mi + 1] = v.y;
                a[4 * mi + 2] = v.z; a[4 * mi + 3] = v.w;
            }
#pragma unroll
            for (int ei = 0; ei < 2; ei++) {
                float4 v = *(const float4*)&Ws[kk][4 * tx + 64 * ei];
                b[4 * ei + 0] = v.x; b[4 * ei + 1] = v.y;
                b[4 * ei + 2] = v.z; b[4 * ei + 3] = v.w;
            }
#pragma unroll
            for (int i = 0; i < 8; i++)
#pragma unroll
                for (int j = 0; j < 8; j++) acc[i][j] += a[i] * b[j];
        }
        __syncthreads();
    }

    float4 bia[2];
    bia[0] = *(const float4*)(bias + e0 + 4 * tx);
    bia[1] = *(const float4*)(bias + e0 + 4 * tx + 64);
#pragma unroll
    for (int mi = 0; mi < 2; mi++)
#pragma unroll
        for (int i = 0; i < 4; i++) {
            int m = m0 + 4 * ty + i + 64 * mi;
#pragma unroll
            for (int ei = 0; ei < 2; ei++) {
                int e = e0 + 4 * tx + 64 * ei;
                float4 v = make_float4(acc[4 * mi + i][4 * ei + 0] + bia[ei].x,
                                       acc[4 * mi + i][4 * ei + 1] + bia[ei].y,
                                       acc[4 * mi + i][4 * ei + 2] + bia[ei].z,
                                       acc[4 * mi + i][4 * ei + 3] + bia[ei].w);
                *(float4*)(out + (size_t)m * DD + e) = v;
            }
        }
}

// ---------------------------------------------------------------------------
extern "C" void kernel_launch(void* const* d_in, const int* in_sizes, int n_in,
                              void* d_out, int out_size) {
    const float* x      = (const float*)d_in[0];
    const float* qkv_w  = (const float*)d_in[1];
    const float* temp   = (const float*)d_in[2];
    const float* proj_w = (const float*)d_in[3];
    const float* proj_b = (const float*)d_in[4];
    float* out = (float*)d_out;

    k_qkv<<<dim3(E3 / 128, ROWS / 128), 256>>>(x, qkv_w);
    k_norm<<<(2 * BH * CC) / 8, 256>>>();
    k_qk<<<dim3(BH, NSPLIT), 256>>>();
    k_softmax<<<BH, 64>>>(temp);
    k_av<<<dim3(BH, (NN + 127) / 128), 256>>>();
    k_proj<<<dim3(DD / 128, ROWS / 128), 256>>>(proj_w, proj_b, out);
}

// round 2
// speedup vs baseline: 1.7518x; 1.7518x over previous
#include <cuda_runtime.h>
#include <math.h>

#define BB 32
#define NN 3136
#define DD 384
#define HH 8
#define CC 48
#define BH 256          // BB*HH
#define ROWS 100352     // BB*NN
#define E3 1152         // 3*DD
#define NSPLIT 7
#define NCHUNK 448      // NN / NSPLIT

// Scratch (sanctioned __device__ globals; no allocations anywhere)
__device__ float g_qkv[(size_t)3 * BH * CC * NN];   // [3][bh][c][n]
__device__ float g_invn[2 * BH * CC];               // inv norms: q rows then k rows
__device__ float g_spart[(size_t)NSPLIT * BH * CC * CC];
__device__ float g_p[(size_t)BH * CC * CC];         // softmaxed attn
__device__ float g_o[(size_t)BH * CC * NN];         // attn @ v, [bh][c][n]

// ---------------------------------------------------------------------------
// tf32 helpers
// ---------------------------------------------------------------------------
__device__ __forceinline__ float tf32r(float f) {
    unsigned r;
    asm("cvt.rna.tf32.f32 %0, %1;" : "=r"(r) : "f"(f));
    return __uint_as_float(r);
}
__device__ __forceinline__ void cvt4(float4& v) {
    v.x = tf32r(v.x); v.y = tf32r(v.y); v.z = tf32r(v.z); v.w = tf32r(v.w);
}
__device__ __forceinline__ void mma_tf32(float* c, const unsigned* a,
                                         const unsigned* b) {
    asm volatile(
        "mma.sync.aligned.m16n8k8.row.col.f32.tf32.tf32.f32 "
        "{%0,%1,%2,%3}, {%4,%5,%6,%7}, {%8,%9}, {%0,%1,%2,%3};\n"
        : "+f"(c[0]), "+f"(c[1]), "+f"(c[2]), "+f"(c[3])
        : "r"(a[0]), "r"(a[1]), "r"(a[2]), "r"(a[3]), "r"(b[0]), "r"(b[1]));
}
#define U(x) __float_as_uint(x)

// ---------------------------------------------------------------------------
// K1: qkv = x @ qkv_w^T via tf32 MMA, scattered into [3][bh][c][n]
// 128x128x32 tile, 256 threads (8 warps, 2x4), warp tile 64x32
// ---------------------------------------------------------------------------
__global__ __launch_bounds__(256) void k_qkv(const float* __restrict__ x,
                                             const float* __restrict__ w) {
    __shared__ float As[128][36];   // [m][k]
    __shared__ float Bs[128][36];   // [e][k]
    const int m0 = blockIdx.y * 128;
    const int e0 = blockIdx.x * 128;
    const int t = threadIdx.x, lane = t & 31, wid = t >> 5;
    const int wm = wid >> 2, wn = wid & 3;
    const int g = lane >> 2, tg = lane & 3;
    const int lr = t >> 3, lc = (t & 7) * 4;

    float acc[16][4];
#pragma unroll
    for (int i = 0; i < 16; i++)
#pragma unroll
        for (int j = 0; j < 4; j++) acc[i][j] = 0.f;

    for (int k0 = 0; k0 < DD; k0 += 32) {
#pragma unroll
        for (int i = 0; i < 4; i++) {
            int r = lr + 32 * i;
            float4 v = *(const float4*)(x + (size_t)(m0 + r) * DD + k0 + lc);
            cvt4(v);
            *(float4*)&As[r][lc] = v;
            float4 u = *(const float4*)(w + (size_t)(e0 + r) * DD + k0 + lc);
            cvt4(u);
            *(float4*)&Bs[r][lc] = u;
        }
        __syncthreads();
#pragma unroll
        for (int kk = 0; kk < 4; kk++) {
            unsigned a[4][4], b[4][2];
#pragma unroll
            for (int mi = 0; mi < 4; mi++) {
                int m = wm * 64 + mi * 16 + g;
                a[mi][0] = U(As[m][kk * 8 + tg]);
                a[mi][1] = U(As[m + 8][kk * 8 + tg]);
                a[mi][2] = U(As[m][kk * 8 + tg + 4]);
                a[mi][3] = U(As[m + 8][kk * 8 + tg + 4]);
            }
#pragma unroll
            for (int ni = 0; ni < 4; ni++) {
                int e = wn * 32 + ni * 8 + g;
                b[ni][0] = U(Bs[e][kk * 8 + tg]);
                b[ni][1] = U(Bs[e][kk * 8 + tg + 4]);
            }
#pragma unroll
            for (int mi = 0; mi < 4; mi++)
#pragma unroll
                for (int ni = 0; ni < 4; ni++)
                    mma_tf32(acc[mi * 4 + ni], a[mi], b[ni]);
        }
        __syncthreads();
    }

    // Epilogue: stage [eL][m] slabs in smem (reuse As), stream n-contiguous
    float (*Cs)[132] = (float (*)[132])&As[0][0];   // 32 x 132
#pragma unroll
    for (int slab = 0; slab < 4; slab++) {
        if (wn == slab) {
#pragma unroll
            for (int mi = 0; mi < 4; mi++)
#pragma unroll
                for (int ni = 0; ni < 4; ni++) {
                    int eL = ni * 8 + 2 * tg;
                    int m = wm * 64 + mi * 16 + g;
                    float* a4 = acc[mi * 4 + ni];
                    Cs[eL][m]         = a4[0];
                    Cs[eL + 1][m]     = a4[1];
                    Cs[eL][m + 8]     = a4[2];
                    Cs[eL + 1][m + 8] = a4[3];
                }
        }
        __syncthreads();
#pragma unroll
        for (int it = 0; it < 4; it++) {
            int idx = t + 256 * it;          // 0..1023
            int eL = idx >> 5, f = idx & 31;
            int e = e0 + slab * 32 + eL;
            int s = e / DD;
            int rem = e - s * DD;
            int h = rem / CC;
            int c = rem - h * CC;
            int m = m0 + 4 * f;
            int b_ = m / NN;
            int n = m - b_ * NN;
            float* dst = g_qkv +
                ((size_t)((s * BB + b_) * HH + h) * CC + c) * NN + n;
            *(float4*)dst = *(float4*)&Cs[eL][4 * f];
        }
        __syncthreads();
    }
}

// ---------------------------------------------------------------------------
// K2: inverse L2 norms of q and k rows (over n). One warp per row.
// ---------------------------------------------------------------------------
__global__ __launch_bounds__(256) void k_norm() {
    int row  = blockIdx.x * 8 + (threadIdx.x >> 5);   // 0..24575
    int lane = threadIdx.x & 31;
    const float4* p = (const float4*)(g_qkv + (size_t)row * NN);
    float s = 0.f;
    for (int i = lane; i < NN / 4; i += 32) {
        float4 v = p[i];
        s += v.x * v.x + v.y * v.y + v.z * v.z + v.w * v.w;
    }
#pragma unroll
    for (int o = 16; o; o >>= 1) s += __shfl_xor_sync(0xffffffffu, s, o);
    if (lane == 0) g_invn[row] = 1.f / fmaxf(sqrtf(s), 1e-12f);
}

// ---------------------------------------------------------------------------
// K3a: partial S[c][d] = sum_n q[c][n] k[d][n] over an n-chunk (deterministic)
// ---------------------------------------------------------------------------
__global__ __launch_bounds__(256) void k_qk() {
    __shared__ float qs[48][68];
    __shared__ float ks[48][68];
    const int bh = blockIdx.x;
    const int n0 = blockIdx.y * NCHUNK;
    const int t  = threadIdx.x;
    const int ci = t >> 4, dj = t & 15;

    const float* qb = g_qkv + (size_t)bh * CC * NN;
    const float* kb = g_qkv + (size_t)(BH + bh) * CC * NN;

    float acc[3][3] = {};
    for (int cc = 0; cc < NCHUNK; cc += 64) {
        int nb = n0 + cc;
#pragma unroll
        for (int jj = 0; jj < 3; jj++) {
            int idx = t + 256 * jj;
            int c = idx >> 4, f = idx & 15;
            *(float4*)&qs[c][4 * f] = *(const float4*)(qb + (size_t)c * NN + nb + 4 * f);
            *(float4*)&ks[c][4 * f] = *(const float4*)(kb + (size_t)c * NN + nb + 4 * f);
        }
        __syncthreads();
#pragma unroll 8
        for (int nn = 0; nn < 64; nn++) {
            float a0 = qs[3 * ci + 0][nn];
            float a1 = qs[3 * ci + 1][nn];
            float a2 = qs[3 * ci + 2][nn];
            float b0 = ks[3 * dj + 0][nn];
            float b1 = ks[3 * dj + 1][nn];
            float b2 = ks[3 * dj + 2][nn];
            acc[0][0] += a0 * b0; acc[0][1] += a0 * b1; acc[0][2] += a0 * b2;
            acc[1][0] += a1 * b0; acc[1][1] += a1 * b1; acc[1][2] += a1 * b2;
            acc[2][0] += a2 * b0; acc[2][1] += a2 * b1; acc[2][2] += a2 * b2;
        }
        __syncthreads();
    }
    float* out = g_spart + ((size_t)blockIdx.y * BH + bh) * (CC * CC);
#pragma unroll
    for (int i = 0; i < 3; i++)
#pragma unroll
        for (int j = 0; j < 3; j++)
            out[(3 * ci + i) * CC + (3 * dj + j)] = acc[i][j];
}

// ---------------------------------------------------------------------------
// K3b: reduce partials, apply inv-norms + temperature, row softmax -> g_p
// ---------------------------------------------------------------------------
__global__ __launch_bounds__(64) void k_softmax(const float* __restrict__ temp) {
    __shared__ float S[48][48];
    const int bh = blockIdx.x;
    const int t  = threadIdx.x;
    const float tp = temp[bh % HH];
    for (int idx = t; idx < CC * CC; idx += 64) {
        float s = 0.f;
#pragma unroll
        for (int p = 0; p < NSPLIT; p++)
            s += g_spart[((size_t)p * BH + bh) * (CC * CC) + idx];
        int c = idx / CC, d = idx - c * CC;
        s *= g_invn[bh * CC + c] * g_invn[BH * CC + bh * CC + d] * tp;
        S[c][d] = s;
    }
    __syncthreads();
    if (t < 48) {
        float mx = -1e30f;
#pragma unroll
        for (int d = 0; d < 48; d++) mx = fmaxf(mx, S[t][d]);
        float sum = 0.f;
#pragma unroll
        for (int d = 0; d < 48; d++) {
            float e = __expf(S[t][d] - mx);
            S[t][d] = e;
            sum += e;
        }
        float inv = 1.f / sum;
#pragma unroll
        for (int d = 0; d < 48; d++)
            g_p[(size_t)bh * (CC * CC) + t * CC + d] = S[t][d] * inv;
    }
}

// ---------------------------------------------------------------------------
// K4: out[c][n] = sum_d P[c][d] * v[d][n]   (per bh, 128-n tiles)
// ---------------------------------------------------------------------------
__global__ __launch_bounds__(256) void k_av() {
    __shared__ float P[48][49];
    __shared__ float Vs[48][132];
    const int bh = blockIdx.x;
    const int n0 = blockIdx.y * 128;
    const int t  = threadIdx.x;
    const int nrem = NN - n0;

    for (int idx = t; idx < CC * CC; idx += 256) {
        int c = idx / CC;
        P[c][idx - c * CC] = g_p[(size_t)bh * (CC * CC) + idx];
    }
    const float* vb = g_qkv + (size_t)(2 * BH + bh) * CC * NN;
#pragma unroll
    for (int jj = 0; jj < 6; jj++) {
        int idx = t + 256 * jj;
        int d = idx >> 5, f = idx & 31;
        if (4 * f < nrem)
            *(float4*)&Vs[d][4 * f] = *(const float4*)(vb + (size_t)d * NN + n0 + 4 * f);
    }
    __syncthreads();

    const int fi = t & 31;
    const int cg = t >> 5;
    if (4 * fi < nrem) {
        float acc[6][4] = {};
#pragma unroll
        for (int d = 0; d < 48; d++) {
            float4 v = *(const float4*)&Vs[d][4 * fi];
#pragma unroll
            for (int i = 0; i < 6; i++) {
                float p = P[6 * cg + i][d];
                acc[i][0] += p * v.x; acc[i][1] += p * v.y;
                acc[i][2] += p * v.z; acc[i][3] += p * v.w;
            }
        }
        float* ob = g_o + (size_t)bh * CC * NN;
#pragma unroll
        for (int i = 0; i < 6; i++)
            *(float4*)(ob + (size_t)(6 * cg + i) * NN + n0 + 4 * fi) =
                make_float4(acc[i][0], acc[i][1], acc[i][2], acc[i][3]);
    }
}

// ---------------------------------------------------------------------------
// K5: final = out_bnd @ proj_w^T + proj_b via tf32 MMA
// A gathered from g_o [bh][c][n]; 128x128x32 tile, 8 warps (2x4), 64x32/warp
// ---------------------------------------------------------------------------
__global__ __launch_bounds__(256) void k_proj(const float* __restrict__ w,
                                              const float* __restrict__ bias,
                                              float* __restrict__ out) {
    __shared__ float As[32][132];   // [k][m]
    __shared__ float Bs[128][36];   // [e][k]
    const int m0 = blockIdx.y * 128;
    const int e0 = blockIdx.x * 128;
    const int t = threadIdx.x, lane = t & 31, wid = t >> 5;
    const int wm = wid >> 2, wn = wid & 3;
    const int g = lane >> 2, tg = lane & 3;
    const int lr = t >> 3, lf = t & 7;

    float acc[16][4];
#pragma unroll
    for (int i = 0; i < 16; i++)
#pragma unroll
        for (int j = 0; j < 4; j++) acc[i][j] = 0.f;

    for (int k0 = 0; k0 < DD; k0 += 32) {
        {
            int k = k0 + lr;              // global k for A row
            int h = k / CC;
            int c = k - h * CC;
#pragma unroll
            for (int i = 0; i < 4; i++) {
                int mloc = 4 * (lf + 8 * i);
                int m = m0 + mloc;
                int b_ = m / NN;
                int n = m - b_ * NN;
                const float* src = g_o +
                    ((size_t)(b_ * HH + h) * CC + c) * NN + n;
                float4 v = *(const float4*)src;
                cvt4(v);
                *(float4*)&As[lr][mloc] = v;
            }
#pragma unroll
            for (int i = 0; i < 4; i++) {
                int r = lr + 32 * i;
                float4 u = *(const float4*)(w + (size_t)(e0 + r) * DD + k0 + 4 * lf);
                cvt4(u);
                *(float4*)&Bs[r][4 * lf] = u;
            }
        }
        __syncthreads();
#pragma unroll
        for (int kk = 0; kk < 4; kk++) {
            unsigned a[4][4], b[4][2];
#pragma unroll
            for (int mi = 0; mi < 4; mi++) {
                int m = wm * 64 + mi * 16 + g;
                a[mi][0] = U(As[kk * 8 + tg][m]);
                a[mi][1] = U(As[kk * 8 + tg][m + 8]);
                a[mi][2] = U(As[kk * 8 + tg + 4][m]);
                a[mi][3] = U(As[kk * 8 + tg + 4][m + 8]);
            }
#pragma unroll
            for (int ni = 0; ni < 4; ni++) {
                int e = wn * 32 + ni * 8 + g;
                b[ni][0] = U(Bs[e][kk * 8 + tg]);
                b[ni][1] = U(Bs[e][kk * 8 + tg + 4]);
            }
#pragma unroll
            for (int mi = 0; mi < 4; mi++)
#pragma unroll
                for (int ni = 0; ni < 4; ni++)
                    mma_tf32(acc[mi * 4 + ni], a[mi], b[ni]);
        }
        __syncthreads();
    }

    // Epilogue: stage [mL][e] slabs (reuse As+Bs space), stream e-contiguous
    float (*Cs)[132] = (float (*)[132])&As[0][0];   // 32 x 132
#pragma unroll
    for (int slab = 0; slab < 4; slab++) {
        if ((slab >> 1) == wm) {
#pragma unroll
            for (int mi2 = 0; mi2 < 2; mi2++) {
                int mi = (slab & 1) * 2 + mi2;
#pragma unroll
                for (int ni = 0; ni < 4; ni++) {
                    int mL = mi2 * 16 + g;
                    int e = wn * 32 + ni * 8 + 2 * tg;
                    float* a4 = acc[mi * 4 + ni];
                    Cs[mL][e]         = a4[0];
                    Cs[mL][e + 1]     = a4[1];
                    Cs[mL + 8][e]     = a4[2];
                    Cs[mL + 8][e + 1] = a4[3];
                }
            }
        }
        __syncthreads();
#pragma unroll
        for (int it = 0; it < 4; it++) {
            int idx = t + 256 * it;
            int mL = idx >> 5, f = idx & 31;
            int m = m0 + slab * 32 + mL;
            float4 v = *(float4*)&Cs[mL][4 * f];
            float4 bi = *(const float4*)(bias + e0 + 4 * f);
            v.x += bi.x; v.y += bi.y; v.z += bi.z; v.w += bi.w;
            *(float4*)(out + (size_t)m * DD + e0 + 4 * f) = v;
        }
        __syncthreads();
    }
}

// ---------------------------------------------------------------------------
extern "C" void kernel_launch(void* const* d_in, const int* in_sizes, int n_in,
                              void* d_out, int out_size) {
    const float* x      = (const float*)d_in[0];
    const float* qkv_w  = (const float*)d_in[1];
    const float* temp   = (const float*)d_in[2];
    const float* proj_w = (const float*)d_in[3];
    const float* proj_b = (const float*)d_in[4];
    float* out = (float*)d_out;

    k_qkv<<<dim3(E3 / 128, ROWS / 128), 256>>>(x, qkv_w);
    k_norm<<<(2 * BH * CC) / 8, 256>>>();
    k_qk<<<dim3(BH, NSPLIT), 256>>>();
    k_softmax<<<BH, 64>>>(temp);
    k_av<<<dim3(BH, (NN + 127) / 128), 256>>>();
    k_proj<<<dim3(DD / 128, ROWS / 128), 256>>>(proj_w, proj_b, out);
}

// round 4
// speedup vs baseline: 2.0146x; 1.1500x over previous
#include <cuda_runtime.h>
#include <cuda_bf16.h>
#include <math.h>
#include <stdint.h>

#define BB 32
#define NN 3136
#define DD 384
#define HH 8
#define CC 48
#define BH 256          // BB*HH
#define ROWS 100352     // BB*NN
#define E3 1152         // 3*DD
#define NSPLIT 7
#define NCHUNK 448      // NN / NSPLIT

// Scratch (sanctioned __device__ globals; no allocations anywhere)
__device__ float g_qkv[(size_t)3 * BH * CC * NN];   // [3][bh][c][n]
__device__ float g_invn[2 * BH * CC];               // inv norms: q rows then k rows
__device__ float g_spart[(size_t)NSPLIT * BH * CC * CC];
__device__ float g_p[(size_t)BH * CC * CC];         // softmaxed attn
__device__ float g_o[(size_t)BH * CC * NN];         // attn @ v, [bh][c][n]

// ---------------------------------------------------------------------------
// helpers
// ---------------------------------------------------------------------------
__device__ __forceinline__ uint32_t smem_u32(const void* p) {
    uint32_t a;
    asm("{ .reg .u64 t; cvta.to.shared.u64 t, %1; cvt.u32.u64 %0, t; }"
        : "=r"(a) : "l"(p));
    return a;
}
__device__ __forceinline__ unsigned cvtu(float f) {   // fp32 -> tf32 bits (rna)
    unsigned r;
    asm("cvt.rna.tf32.f32 %0, %1;" : "=r"(r) : "f"(f));
    return r;
}
__device__ __forceinline__ void mma_tf32(float* c, const unsigned* a,
                                         const unsigned* b) {
    asm volatile(
        "mma.sync.aligned.m16n8k8.row.col.f32.tf32.tf32.f32 "
        "{%0,%1,%2,%3}, {%4,%5,%6,%7}, {%8,%9}, {%0,%1,%2,%3};\n"
        : "+f"(c[0]), "+f"(c[1]), "+f"(c[2]), "+f"(c[3])
        : "r"(a[0]), "r"(a[1]), "r"(a[2]), "r"(a[3]), "r"(b[0]), "r"(b[1]));
}
__device__ __forceinline__ void cpa16(uint32_t s, const float* g) {
    asm volatile("cp.async.ca.shared.global [%0], [%1], 16;"
                 :: "r"(s), "l"(g) : "memory");
}
#define CPA_COMMIT() asm volatile("cp.async.commit_group;" ::: "memory")
#define CPA_WAIT1()  asm volatile("cp.async.wait_group 1;" ::: "memory")
#define CPA_WAIT0()  asm volatile("cp.async.wait_group 0;" ::: "memory")

// ---------------------------------------------------------------------------
// K1: qkv = x @ qkv_w^T via tf32 MMA + cp.async double buffering
// 128x128 tile, K in 12 chunks of 32; 8 warps (2x4), warp tile 64x32
// dyn smem: As[2][128][36], Bs[2][128][36]
// ---------------------------------------------------------------------------
__global__ __launch_bounds__(256) void k_qkv(const float* __restrict__ x,
                                             const float* __restrict__ w) {
    extern __shared__ float ds[];
    float (*As)[128][36] = (float (*)[128][36])ds;
    float (*Bs)[128][36] = (float (*)[128][36])(ds + 2 * 128 * 36);
    const int m0 = blockIdx.y * 128, e0 = blockIdx.x * 128;
    const int t = threadIdx.x, lane = t & 31, wid = t >> 5;
    const int wm = wid >> 2, wn = wid & 3;
    const int g = lane >> 2, tg = lane & 3;
    const int lr = t >> 3, ls = (t & 7) * 4;

    const float* gx = x + (size_t)(m0 + lr) * DD + ls;
    const float* gw = w + (size_t)(e0 + lr) * DD + ls;

    float acc[16][4];
#pragma unroll
    for (int i = 0; i < 16; i++)
#pragma unroll
        for (int j = 0; j < 4; j++) acc[i][j] = 0.f;

#define ISSUE_QKV(buf, k0)                                                   \
    do {                                                                     \
        _Pragma("unroll")                                                    \
        for (int i = 0; i < 4; i++) {                                        \
            cpa16(smem_u32(&As[buf][lr + 32 * i][ls]),                       \
                  gx + (size_t)(32 * i) * DD + (k0));                        \
            cpa16(smem_u32(&Bs[buf][lr + 32 * i][ls]),                       \
                  gw + (size_t)(32 * i) * DD + (k0));                        \
        }                                                                    \
    } while (0)

    ISSUE_QKV(0, 0);
    CPA_COMMIT();

    for (int ch = 0; ch < 12; ch++) {
        const int buf = ch & 1;
        if (ch < 11) {
            ISSUE_QKV(buf ^ 1, (ch + 1) * 32);
            CPA_COMMIT();
            CPA_WAIT1();
        } else {
            CPA_WAIT0();
        }
        __syncthreads();
#pragma unroll
        for (int kk = 0; kk < 4; kk++) {
            unsigned a[4][4], b[4][2];
#pragma unroll
            for (int mi = 0; mi < 4; mi++) {
                int m = wm * 64 + mi * 16 + g;
                a[mi][0] = cvtu(As[buf][m][kk * 8 + tg]);
                a[mi][1] = cvtu(As[buf][m + 8][kk * 8 + tg]);
                a[mi][2] = cvtu(As[buf][m][kk * 8 + tg + 4]);
                a[mi][3] = cvtu(As[buf][m + 8][kk * 8 + tg + 4]);
            }
#pragma unroll
            for (int ni = 0; ni < 4; ni++) {
                int e = wn * 32 + ni * 8 + g;
                b[ni][0] = cvtu(Bs[buf][e][kk * 8 + tg]);
                b[ni][1] = cvtu(Bs[buf][e][kk * 8 + tg + 4]);
            }
#pragma unroll
            for (int mi = 0; mi < 4; mi++)
#pragma unroll
                for (int ni = 0; ni < 4; ni++)
                    mma_tf32(acc[mi * 4 + ni], a[mi], b[ni]);
        }
        __syncthreads();
    }
#undef ISSUE_QKV

    // Epilogue: stage [eL][m] slabs in smem, stream n-contiguous scatter
    float (*Cs)[132] = (float (*)[132])ds;   // 32 x 132
#pragma unroll 1
    for (int slab = 0; slab < 4; slab++) {
        if (wn == slab) {
#pragma unroll
            for (int mi = 0; mi < 4; mi++)
#pragma unroll
                for (int ni = 0; ni < 4; ni++) {
                    int eL = ni * 8 + 2 * tg;
                    int m = wm * 64 + mi * 16 + g;
                    float* a4 = acc[mi * 4 + ni];
                    Cs[eL][m]         = a4[0];
                    Cs[eL + 1][m]     = a4[1];
                    Cs[eL][m + 8]     = a4[2];
                    Cs[eL + 1][m + 8] = a4[3];
                }
        }
        __syncthreads();
#pragma unroll
        for (int it = 0; it < 4; it++) {
            int idx = t + 256 * it;          // 0..1023
            int eL = idx >> 5, f = idx & 31;
            int e = e0 + slab * 32 + eL;
            int s = e / DD;
            int rem = e - s * DD;
            int h = rem / CC;
            int c = rem - h * CC;
            int m = m0 + 4 * f;
            int b_ = m / NN;
            int n = m - b_ * NN;
            *(float4*)(g_qkv + ((size_t)((s * BB + b_) * HH + h) * CC + c) * NN + n) =
                *(float4*)&Cs[eL][4 * f];
        }
        __syncthreads();
    }
}

// ---------------------------------------------------------------------------
// K2: inverse L2 norms of q and k rows (over n). One warp per row.
// ---------------------------------------------------------------------------
__global__ __launch_bounds__(256) void k_norm() {
    int row  = blockIdx.x * 8 + (threadIdx.x >> 5);
    int lane = threadIdx.x & 31;
    const float4* p = (const float4*)(g_qkv + (size_t)row * NN);
    float s = 0.f;
    for (int i = lane; i < NN / 4; i += 32) {
        float4 v = p[i];
        s += v.x * v.x + v.y * v.y + v.z * v.z + v.w * v.w;
    }
#pragma unroll
    for (int o = 16; o; o >>= 1) s += __shfl_xor_sync(0xffffffffu, s, o);
    if (lane == 0) g_invn[row] = 1.f / fmaxf(sqrtf(s), 1e-12f);
}

// ---------------------------------------------------------------------------
// K3a: partial S[c][d] = sum_n q[c][n] k[d][n] over an n-chunk
// ---------------------------------------------------------------------------
__global__ __launch_bounds__(256) void k_qk() {
    __shared__ float qs[48][68];
    __shared__ float ks[48][68];
    const int bh = blockIdx.x;
    const int n0 = blockIdx.y * NCHUNK;
    const int t  = threadIdx.x;
    const int ci = t >> 4, dj = t & 15;

    const float* qb = g_qkv + (size_t)bh * CC * NN;
    const float* kb = g_qkv + (size_t)(BH + bh) * CC * NN;

    float acc[3][3] = {};
    for (int cc = 0; cc < NCHUNK; cc += 64) {
        int nb = n0 + cc;
#pragma unroll
        for (int jj = 0; jj < 3; jj++) {
            int idx = t + 256 * jj;
            int c = idx >> 4, f = idx & 15;
            *(float4*)&qs[c][4 * f] = *(const float4*)(qb + (size_t)c * NN + nb + 4 * f);
            *(float4*)&ks[c][4 * f] = *(const float4*)(kb + (size_t)c * NN + nb + 4 * f);
        }
        __syncthreads();
#pragma unroll 8
        for (int nn = 0; nn < 64; nn++) {
            float a0 = qs[3 * ci + 0][nn];
            float a1 = qs[3 * ci + 1][nn];
            float a2 = qs[3 * ci + 2][nn];
            float b0 = ks[3 * dj + 0][nn];
            float b1 = ks[3 * dj + 1][nn];
            float b2 = ks[3 * dj + 2][nn];
            acc[0][0] += a0 * b0; acc[0][1] += a0 * b1; acc[0][2] += a0 * b2;
            acc[1][0] += a1 * b0; acc[1][1] += a1 * b1; acc[1][2] += a1 * b2;
            acc[2][0] += a2 * b0; acc[2][1] += a2 * b1; acc[2][2] += a2 * b2;
        }
        __syncthreads();
    }
    float* out = g_spart + ((size_t)blockIdx.y * BH + bh) * (CC * CC);
#pragma unroll
    for (int i = 0; i < 3; i++)
#pragma unroll
        for (int j = 0; j < 3; j++)
            out[(3 * ci + i) * CC + (3 * dj + j)] = acc[i][j];
}

// ---------------------------------------------------------------------------
// K3b: reduce partials, apply inv-norms + temperature, row softmax -> g_p
// ---------------------------------------------------------------------------
__global__ __launch_bounds__(64) void k_softmax(const float* __restrict__ temp) {
    __shared__ float S[48][48];
    const int bh = blockIdx.x;
    const int t  = threadIdx.x;
    const float tp = temp[bh % HH];
    for (int idx = t; idx < CC * CC; idx += 64) {
        float s = 0.f;
#pragma unroll
        for (int p = 0; p < NSPLIT; p++)
            s += g_spart[((size_t)p * BH + bh) * (CC * CC) + idx];
        int c = idx / CC, d = idx - c * CC;
        s *= g_invn[bh * CC + c] * g_invn[BH * CC + bh * CC + d] * tp;
        S[c][d] = s;
    }
    __syncthreads();
    if (t < 48) {
        float mx = -1e30f;
#pragma unroll
        for (int d = 0; d < 48; d++) mx = fmaxf(mx, S[t][d]);
        float sum = 0.f;
#pragma unroll
        for (int d = 0; d < 48; d++) {
            float e = __expf(S[t][d] - mx);
            S[t][d] = e;
            sum += e;
        }
        float inv = 1.f / sum;
#pragma unroll
        for (int d = 0; d < 48; d++)
            g_p[(size_t)bh * (CC * CC) + t * CC + d] = S[t][d] * inv;
    }
}

// ---------------------------------------------------------------------------
// K4: out[c][n] = sum_d P[c][d] * v[d][n]
// ---------------------------------------------------------------------------
__global__ __launch_bounds__(256) void k_av() {
    __shared__ float P[48][49];
    __shared__ float Vs[48][132];
    const int bh = blockIdx.x;
    const int n0 = blockIdx.y * 128;
    const int t  = threadIdx.x;
    const int nrem = NN - n0;

    for (int idx = t; idx < CC * CC; idx += 256) {
        int c = idx / CC;
        P[c][idx - c * CC] = g_p[(size_t)bh * (CC * CC) + idx];
    }
    const float* vb = g_qkv + (size_t)(2 * BH + bh) * CC * NN;
#pragma unroll
    for (int jj = 0; jj < 6; jj++) {
        int idx = t + 256 * jj;
        int d = idx >> 5, f = idx & 31;
        if (4 * f < nrem)
            *(float4*)&Vs[d][4 * f] = *(const float4*)(vb + (size_t)d * NN + n0 + 4 * f);
    }
    __syncthreads();

    const int fi = t & 31;
    const int cg = t >> 5;
    if (4 * fi < nrem) {
        float acc[6][4] = {};
#pragma unroll
        for (int d = 0; d < 48; d++) {
            float4 v = *(const float4*)&Vs[d][4 * fi];
#pragma unroll
            for (int i = 0; i < 6; i++) {
                float p = P[6 * cg + i][d];
                acc[i][0] += p * v.x; acc[i][1] += p * v.y;
                acc[i][2] += p * v.z; acc[i][3] += p * v.w;
            }
        }
        float* ob = g_o + (size_t)bh * CC * NN;
#pragma unroll
        for (int i = 0; i < 6; i++)
            *(float4*)(ob + (size_t)(6 * cg + i) * NN + n0 + 4 * fi) =
                make_float4(acc[i][0], acc[i][1], acc[i][2], acc[i][3]);
    }
}

// ---------------------------------------------------------------------------
// K5: final = out_bnd @ proj_w^T + proj_b via tf32 MMA + cp.async
// A gathered from g_o into [k][m] tile (pad 136); B [e][k] (pad 36)
// dyn smem: As2[2][32][136], Bs[2][128][36]
// ---------------------------------------------------------------------------
__global__ __launch_bounds__(256) void k_proj(const float* __restrict__ w,
                                              const float* __restrict__ bias,
                                              float* __restrict__ out) {
    extern __shared__ float ds[];
    float (*As2)[32][136] = (float (*)[32][136])ds;
    float (*Bs)[128][36]  = (float (*)[128][36])(ds + 2 * 32 * 136);
    const int m0 = blockIdx.y * 128, e0 = blockIdx.x * 128;
    const int t = threadIdx.x, lane = t & 31, wid = t >> 5;
    const int wm = wid >> 2, wn = wid & 3;
    const int g = lane >> 2, tg = lane & 3;
    const int lr = t >> 3, ls = (t & 7) * 4;

    const float* gw = w + (size_t)(e0 + lr) * DD + ls;

    float acc[16][4];
#pragma unroll
    for (int i = 0; i < 16; i++)
#pragma unroll
        for (int j = 0; j < 4; j++) acc[i][j] = 0.f;

#define ISSUE_PROJ(buf, k0)                                                  \
    do {                                                                     \
        _Pragma("unroll")                                                    \
        for (int i = 0; i < 4; i++) {                                        \
            int idx = t + 256 * i;                                           \
            int kloc = idx >> 5, m4 = idx & 31;                              \
            int kg = (k0) + kloc;                                            \
            int h = kg / CC, c = kg - h * CC;                                \
            int m = m0 + 4 * m4;                                             \
            int b_ = m / NN, n = m - b_ * NN;                                \
            cpa16(smem_u32(&As2[buf][kloc][4 * m4]),                         \
                  g_o + ((size_t)(b_ * HH + h) * CC + c) * NN + n);          \
            cpa16(smem_u32(&Bs[buf][lr + 32 * i][ls]),                       \
                  gw + (size_t)(32 * i) * DD + (k0));                        \
        }                                                                    \
    } while (0)

    ISSUE_PROJ(0, 0);
    CPA_COMMIT();

    for (int ch = 0; ch < 12; ch++) {
        const int buf = ch & 1;
        if (ch < 11) {
            ISSUE_PROJ(buf ^ 1, (ch + 1) * 32);
            CPA_COMMIT();
            CPA_WAIT1();
        } else {
            CPA_WAIT0();
        }
        __syncthreads();
#pragma unroll
        for (int kk = 0; kk < 4; kk++) {
            unsigned a[4][4], b[4][2];
#pragma unroll
            for (int mi = 0; mi < 4; mi++) {
                int m = wm * 64 + mi * 16 + g;
                a[mi][0] = cvtu(As2[buf][kk * 8 + tg][m]);
                a[mi][1] = cvtu(As2[buf][kk * 8 + tg][m + 8]);
                a[mi][2] = cvtu(As2[buf][kk * 8 + tg + 4][m]);
                a[mi][3] = cvtu(As2[buf][kk * 8 + tg + 4][m + 8]);
            }
#pragma unroll
            for (int ni = 0; ni < 4; ni++) {
                int e = wn * 32 + ni * 8 + g;
                b[ni][0] = cvtu(Bs[buf][e][kk * 8 + tg]);
                b[ni][1] = cvtu(Bs[buf][e][kk * 8 + tg + 4]);
            }
#pragma unroll
            for (int mi = 0; mi < 4; mi++)
#pragma unroll
                for (int ni = 0; ni < 4; ni++)
                    mma_tf32(acc[mi * 4 + ni], a[mi], b[ni]);
        }
        __syncthreads();
    }
#undef ISSUE_PROJ

    // Epilogue: stage [mL][e] slabs, stream e-contiguous + bias
    float (*Cs)[132] = (float (*)[132])ds;   // 32 x 132
#pragma unroll 1
    for (int slab = 0; slab < 4; slab++) {
        if ((slab >> 1) == wm) {
#pragma unroll
            for (int mi2 = 0; mi2 < 2; mi2++) {
                int mi = (slab & 1) * 2 + mi2;
#pragma unroll
                for (int ni = 0; ni < 4; ni++) {
                    int mL = mi2 * 16 + g;
                    int e = wn * 32 + ni * 8 + 2 * tg;
                    float* a4 = acc[mi * 4 + ni];
                    Cs[mL][e]         = a4[0];
                    Cs[mL][e + 1]     = a4[1];
                    Cs[mL + 8][e]     = a4[2];
                    Cs[mL + 8][e + 1] = a4[3];
                }
            }
        }
        __syncthreads();
#pragma unroll
        for (int it = 0; it < 4; it++) {
            int idx = t + 256 * it;
            int mL = idx >> 5, f = idx & 31;
            int m = m0 + slab * 32 + mL;
            float4 v = *(float4*)&Cs[mL][4 * f];
            float4 bi = *(const float4*)(bias + e0 + 4 * f);
            v.x += bi.x; v.y += bi.y; v.z += bi.z; v.w += bi.w;
            *(float4*)(out + (size_t)m * DD + e0 + 4 * f) = v;
        }
        __syncthreads();
    }
}

// ---------------------------------------------------------------------------
#define SMEM_QKV (2 * 128 * 36 * 2 * 4)                  // 73728 B
#define SMEM_PROJ ((2 * 32 * 136 + 2 * 128 * 36) * 4)    // 71680 B

extern "C" void kernel_launch(void* const* d_in, const int* in_sizes, int n_in,
                              void* d_out, int out_size) {
    const float* x      = (const float*)d_in[0];
    const float* qkv_w  = (const float*)d_in[1];
    const float* temp   = (const float*)d_in[2];
    const float* proj_w = (const float*)d_in[3];
    const float* proj_b = (const float*)d_in[4];
    float* out = (float*)d_out;

    static int configured = 0;
    if (!configured) {
        cudaFuncSetAttribute(k_qkv,  cudaFuncAttributeMaxDynamicSharedMemorySize, SMEM_QKV);
        cudaFuncSetAttribute(k_proj, cudaFuncAttributeMaxDynamicSharedMemorySize, SMEM_PROJ);
        configured = 1;
    }

    k_qkv<<<dim3(E3 / 128, ROWS / 128), 256, SMEM_QKV>>>(x, qkv_w);
    k_norm<<<(2 * BH * CC) / 8, 256>>>();
    k_qk<<<dim3(BH, NSPLIT), 256>>>();
    k_softmax<<<BH, 64>>>(temp);
    k_av<<<dim3(BH, (NN + 127) / 128), 256>>>();
    k_proj<<<dim3(DD / 128, ROWS / 128), 256, SMEM_PROJ>>>(proj_w, proj_b, out);
}